// round 5
// baseline (speedup 1.0000x reference)
#include <cuda_runtime.h>
#include <cuda_bf16.h>
#include <math.h>

// ---------------- problem constants ----------------
#define BB    8
#define FREQ  257
#define TT    1345
#define NF    128
#define NS    64
#define NW    20          // (1345-128-1)/64 + 1
#define WIN   (BB*NW)     // 160
#define C1    8
#define P1H   84
#define P1W   41
#define C2    16
#define P2H   28
#define P2W   14
#define HID   6272        // 16*28*14
#define G3    (3*HID)     // 18816

#define GRU_BLOCKS 148
#define GRU_SLOTS  (GRU_BLOCKS*16)          // 2368 warp slots
#define GRU_SMEM   (4*HID*(int)sizeof(float2))   // 200704 B

// packed fp32x2 FMA: acc = a*b + acc (two full-precision fp32 FMAs, 1 instr)
#define FFMA2ACC(acc, a, b) asm("fma.rn.f32x2 %0, %1, %2, %0;" \
    : "+l"(*(unsigned long long*)&(acc)) \
    : "l"(*(const unsigned long long*)&(a)), "l"(*(const unsigned long long*)&(b)))

// ---------------- device scratch (no allocation allowed) ----------------
__device__ float g_P1[WIN * C1 * P1H * P1W];   // 160*8*84*41
__device__ float g_FEATS[WIN * HID];           // 160*6272
__device__ float g_GI[(size_t)WIN * G3];       // 160*18816
__device__ float g_H[2][BB * HID];             // ping-pong hidden state

// =====================================================================
// K1: conv1 (1->8ch, 9x9, pad2) + maxpool3 + leaky_relu, fused.
// =====================================================================
__global__ void conv1_kernel(const float* __restrict__ x,
                             const float* __restrict__ w,
                             const float* __restrict__ bias)
{
    __shared__ float tile[11][132];
    __shared__ float Ws[C1][9][9];

    const int pr  = blockIdx.x;        // pooled row 0..83
    const int win = blockIdx.y;        // 0..159
    const int b   = win / NW;
    const int wdx = win % NW;
    const int tid = threadIdx.y * 41 + threadIdx.x;   // 0..327

    for (int i = tid; i < C1 * 81; i += 328)
        ((float*)Ws)[i] = w[i];

    const float* xb = x + (size_t)b * FREQ * TT + TT + wdx * NS;
    const int r0 = 3 * pr - 2;
    for (int i = tid; i < 11 * 132; i += 328) {
        int r = i / 132, c = i % 132;
        int gr = r0 + r, gc = c - 2;
        float v = 0.f;
        if (gr >= 0 && gr < 256 && gc >= 0 && gc < NF)
            v = xb[(size_t)gr * TT + gc];
        tile[r][c] = v;
    }
    __syncthreads();

    const int ch = threadIdx.y;
    const int tc = threadIdx.x;
    const float bv = bias[ch];
    float acc[3][3];
#pragma unroll
    for (int i = 0; i < 3; i++)
#pragma unroll
        for (int j = 0; j < 3; j++) acc[i][j] = bv;

#pragma unroll
    for (int r = 0; r < 11; r++) {
        float v[11];
#pragma unroll
        for (int m = 0; m < 11; m++) v[m] = tile[r][3 * tc + m];
#pragma unroll
        for (int i = 0; i < 3; i++) {
            const int kr = r - i;
            if (kr >= 0 && kr <= 8) {
#pragma unroll
                for (int kc = 0; kc < 9; kc++) {
                    float wv = Ws[ch][kr][kc];
                    acc[i][0] = fmaf(wv, v[kc],     acc[i][0]);
                    acc[i][1] = fmaf(wv, v[kc + 1], acc[i][1]);
                    acc[i][2] = fmaf(wv, v[kc + 2], acc[i][2]);
                }
            }
        }
    }
    float m = acc[0][0];
#pragma unroll
    for (int i = 0; i < 3; i++)
#pragma unroll
        for (int j = 0; j < 3; j++) m = fmaxf(m, acc[i][j]);
    float o = (m > 0.f) ? m : 0.01f * m;
    g_P1[(((size_t)win * C1 + ch) * P1H + pr) * P1W + tc] = o;
}

// =====================================================================
// K2: conv2 (8->16ch, 4x4, pad2) + maxpool3 + leaky_relu, fused.
// =====================================================================
__global__ void conv2_kernel(const float* __restrict__ w,
                             const float* __restrict__ bias)
{
    __shared__ float tile[C1][6][46];
    __shared__ float Ws[C2][C1][4][4];

    const int pr  = blockIdx.x;
    const int win = blockIdx.y;
    const int tid = threadIdx.y * 14 + threadIdx.x;   // 0..223

    for (int i = tid; i < C2 * C1 * 16; i += 224)
        ((float*)Ws)[i] = w[i];

    const float* src = g_P1 + (size_t)win * C1 * P1H * P1W;
    const int r0 = 3 * pr - 2;
    for (int i = tid; i < C1 * 6 * 46; i += 224) {
        int ich = i / (6 * 46);
        int rem = i % (6 * 46);
        int r = rem / 46, c = rem % 46;
        int gr = r0 + r, gc = c - 2;
        float v = 0.f;
        if (gr >= 0 && gr < P1H && gc >= 0 && gc < P1W)
            v = src[((size_t)ich * P1H + gr) * P1W + gc];
        tile[ich][r][c] = v;
    }
    __syncthreads();

    const int pc = threadIdx.x;
    const int oc = threadIdx.y;
    const float bv = bias[oc];
    float acc[3][3];
#pragma unroll
    for (int i = 0; i < 3; i++)
#pragma unroll
        for (int j = 0; j < 3; j++) acc[i][j] = bv;

#pragma unroll
    for (int ich = 0; ich < C1; ich++) {
#pragma unroll
        for (int r = 0; r < 6; r++) {
            float v[6];
#pragma unroll
            for (int m = 0; m < 6; m++) v[m] = tile[ich][r][3 * pc + m];
#pragma unroll
            for (int i = 0; i < 3; i++) {
                const int kr = r - i;
                if (kr >= 0 && kr <= 3) {
#pragma unroll
                    for (int kc = 0; kc < 4; kc++) {
                        float wv = Ws[oc][ich][kr][kc];
                        acc[i][0] = fmaf(wv, v[kc],     acc[i][0]);
                        acc[i][1] = fmaf(wv, v[kc + 1], acc[i][1]);
                        acc[i][2] = fmaf(wv, v[kc + 2], acc[i][2]);
                    }
                }
            }
        }
    }
    float m = acc[0][0];
#pragma unroll
    for (int i = 0; i < 3; i++)
#pragma unroll
        for (int j = 0; j < 3; j++) m = fmaxf(m, acc[i][j]);
    float o = (m > 0.f) ? m : 0.01f * m;
    g_FEATS[(size_t)win * HID + oc * (P2H * P2W) + pr * P2W + pc] = o;
}

// =====================================================================
// K3: GI = FEATS(160x6272) @ w_ih^T(6272x18816) + b_ih
// BM=160, BN=128, BK=16; 256 threads; 10x8 per thread with FFMA2 (N-pairs).
// =====================================================================
__global__ __launch_bounds__(256, 2)
void gi_gemm_kernel(const float* __restrict__ Wih,
                    const float* __restrict__ bih)
{
    __shared__ float As[16][160];
    __shared__ float Bs[16][128];

    const int n0 = blockIdx.x * 128;
    const int tid = threadIdx.x;
    const int ty = tid >> 4;      // 0..15 -> M group (10 rows)
    const int tx = tid & 15;      // 0..15 -> N group (8 cols = 4 pairs)

    float2 acc[10][4];
#pragma unroll
    for (int i = 0; i < 10; i++)
#pragma unroll
        for (int u = 0; u < 4; u++) acc[i][u] = make_float2(0.f, 0.f);

    for (int k0 = 0; k0 < HID; k0 += 16) {
#pragma unroll
        for (int l = 0; l < 10; l++) {
            int idx = tid + l * 256;          // 0..2559
            int m = idx >> 4, kk = idx & 15;
            As[kk][m] = g_FEATS[(size_t)m * HID + k0 + kk];
        }
#pragma unroll
        for (int l = 0; l < 8; l++) {
            int idx = tid + l * 256;          // 0..2047
            int n = idx >> 4, kk = idx & 15;
            Bs[kk][n] = __ldcs(&Wih[(size_t)(n0 + n) * HID + k0 + kk]);
        }
        __syncthreads();

#pragma unroll
        for (int kk = 0; kk < 16; kk++) {
            const float2* bs2 = reinterpret_cast<const float2*>(&Bs[kk][tx * 8]);
            float2 b0 = bs2[0], b1 = bs2[1], b2 = bs2[2], b3 = bs2[3];
#pragma unroll
            for (int i = 0; i < 10; i++) {
                float av = As[kk][ty * 10 + i];
                float2 a2 = make_float2(av, av);
                FFMA2ACC(acc[i][0], a2, b0);
                FFMA2ACC(acc[i][1], a2, b1);
                FFMA2ACC(acc[i][2], a2, b2);
                FFMA2ACC(acc[i][3], a2, b3);
            }
        }
        __syncthreads();
    }

#pragma unroll
    for (int i = 0; i < 10; i++) {
        int m = ty * 10 + i;
#pragma unroll
        for (int u = 0; u < 4; u++) {
            int n = n0 + tx * 8 + 2 * u;
            g_GI[(size_t)m * G3 + n]     = acc[i][u].x + bih[n];
            g_GI[(size_t)m * G3 + n + 1] = acc[i][u].y + bih[n + 1];
        }
    }
}

// =====================================================================
// K4: one GRU step. grid 148, block 512 (16 warps), h fully resident in
// 200KB dynamic smem as batch-paired float2. Warp -> hidden unit j
// (up to 3 units per warp), 3 gates x 4 batch-pairs via FFMA2.
// =====================================================================
__global__ __launch_bounds__(512, 1)
void gru_step_kernel(const float* __restrict__ Whh,
                     const float* __restrict__ bhh,
                     const float* __restrict__ h0,
                     int t)
{
    extern __shared__ float2 hp[];   // [4][HID]: hp[p][k] = {h[2p][k], h[2p+1][k]}

    const float* hin  = (t == 0) ? h0 : g_H[(t + 1) & 1];
    float*       hout = g_H[t & 1];
    const int tid = threadIdx.x;

    // fill paired h: 200KB, coalesced float4 reads
#pragma unroll
    for (int p = 0; p < 4; p++) {
        const float4* r0 = (const float4*)(hin + (size_t)(2 * p) * HID);
        const float4* r1 = (const float4*)(hin + (size_t)(2 * p + 1) * HID);
        for (int q = tid; q < HID / 4; q += 512) {
            float4 a = r0[q], b = r1[q];
            float2* dst = &hp[p * HID + q * 4];
            dst[0] = make_float2(a.x, b.x);
            dst[1] = make_float2(a.y, b.y);
            dst[2] = make_float2(a.z, b.z);
            dst[3] = make_float2(a.w, b.w);
        }
    }
    __syncthreads();

    const int warpId = tid >> 5;
    const int lane   = tid & 31;
    const int slot   = warpId * GRU_BLOCKS + blockIdx.x;   // balanced: 0..2367

#pragma unroll 1
    for (int s = 0; s < 3; s++) {
        const int j = slot + GRU_SLOTS * s;
        if (j >= HID) break;

        const float* wr = Whh + (size_t)j * HID;
        const float* wz = wr + (size_t)HID * HID;
        const float* wn = wz + (size_t)HID * HID;

        float2 aR[4], aZ[4], aN[4];
#pragma unroll
        for (int p = 0; p < 4; p++) {
            aR[p] = make_float2(0.f, 0.f);
            aZ[p] = make_float2(0.f, 0.f);
            aN[p] = make_float2(0.f, 0.f);
        }

#pragma unroll 7
        for (int kk = 0; kk < HID / 32; kk++) {
            const int k = kk * 32 + lane;
            float wrv = __ldcs(wr + k);
            float wzv = __ldcs(wz + k);
            float wnv = __ldcs(wn + k);
            float2 wr2 = make_float2(wrv, wrv);
            float2 wz2 = make_float2(wzv, wzv);
            float2 wn2 = make_float2(wnv, wnv);
#pragma unroll
            for (int p = 0; p < 4; p++) {
                float2 hv = hp[p * HID + k];
                FFMA2ACC(aR[p], wr2, hv);
                FFMA2ACC(aZ[p], wz2, hv);
                FFMA2ACC(aN[p], wn2, hv);
            }
        }

        // butterfly reduce all 24 components across the warp
#pragma unroll
        for (int p = 0; p < 4; p++) {
#pragma unroll
            for (int off = 16; off > 0; off >>= 1) {
                aR[p].x += __shfl_xor_sync(0xffffffffu, aR[p].x, off);
                aR[p].y += __shfl_xor_sync(0xffffffffu, aR[p].y, off);
                aZ[p].x += __shfl_xor_sync(0xffffffffu, aZ[p].x, off);
                aZ[p].y += __shfl_xor_sync(0xffffffffu, aZ[p].y, off);
                aN[p].x += __shfl_xor_sync(0xffffffffu, aN[p].x, off);
                aN[p].y += __shfl_xor_sync(0xffffffffu, aN[p].y, off);
            }
        }

        if (lane < BB) {
            const int b = lane, p = b >> 1;
            const bool hi = b & 1;
            float hr = (hi ? aR[p].y : aR[p].x) + bhh[j];
            float hz = (hi ? aZ[p].y : aZ[p].x) + bhh[j + HID];
            float hn = (hi ? aN[p].y : aN[p].x) + bhh[j + 2 * HID];
            const float* gib = g_GI + (size_t)(b * NW + t) * G3;
            float r = 1.f / (1.f + expf(-(gib[j] + hr)));
            float z = 1.f / (1.f + expf(-(gib[j + HID] + hz)));
            float n = tanhf(gib[j + 2 * HID] + r * hn);
            float2 hj = hp[p * HID + j];
            float ho = hi ? hj.y : hj.x;
            hout[(size_t)b * HID + j] = (1.f - z) * n + z * ho;
        }
    }
}

// =====================================================================
// K5: samples = h @ fc2_w^T + fc2_b ; labels (int32) appended as float32.
// =====================================================================
__global__ void final_fc_kernel(const float* __restrict__ fw,
                                const float* __restrict__ fb,
                                const int* __restrict__ labels,
                                float* __restrict__ out)
{
    const float* h = g_H[(NW - 1) & 1];   // g_H[1]
    const int warpId = threadIdx.x >> 5;
    const int lane   = threadIdx.x & 31;

    for (int p = warpId; p < BB * 10; p += 8) {
        int b = p / 10, c = p % 10;
        const float* hb = h + (size_t)b * HID;
        const float* wc = fw + (size_t)c * HID;
        float s = 0.f;
        for (int k = lane; k < HID; k += 32)
            s = fmaf(hb[k], wc[k], s);
#pragma unroll
        for (int off = 16; off > 0; off >>= 1)
            s += __shfl_xor_sync(0xffffffffu, s, off);
        if (lane == 0)
            out[b * 10 + c] = s + fb[c];
    }
    if (threadIdx.x < BB)
        out[BB * 10 + threadIdx.x] = (float)labels[threadIdx.x];
}

// =====================================================================
extern "C" void kernel_launch(void* const* d_in, const int* in_sizes, int n_in,
                              void* d_out, int out_size)
{
    const float* x       = (const float*)d_in[0];
    const int*   labels  = (const int*)d_in[1];
    const float* h0      = (const float*)d_in[2];
    const float* conv1_w = (const float*)d_in[3];
    const float* conv1_b = (const float*)d_in[4];
    const float* conv2_w = (const float*)d_in[5];
    const float* conv2_b = (const float*)d_in[6];
    const float* w_ih    = (const float*)d_in[7];
    const float* w_hh    = (const float*)d_in[8];
    const float* b_ih    = (const float*)d_in[9];
    const float* b_hh    = (const float*)d_in[10];
    const float* fc2_w   = (const float*)d_in[11];
    const float* fc2_b   = (const float*)d_in[12];
    float*       out     = (float*)d_out;

    cudaFuncSetAttribute(gru_step_kernel,
                         cudaFuncAttributeMaxDynamicSharedMemorySize, GRU_SMEM);

    conv1_kernel<<<dim3(P1H, WIN), dim3(41, 8)>>>(x, conv1_w, conv1_b);
    conv2_kernel<<<dim3(P2H, WIN), dim3(14, 16)>>>(conv2_w, conv2_b);
    gi_gemm_kernel<<<G3 / 128, 256>>>(w_ih, b_ih);
    for (int t = 0; t < NW; t++)
        gru_step_kernel<<<GRU_BLOCKS, 512, GRU_SMEM>>>(w_hh, b_hh, h0, t);
    final_fc_kernel<<<1, 256>>>(fc2_w, fc2_b, labels, out);
}

// round 6
// speedup vs baseline: 1.4167x; 1.4167x over previous
#include <cuda_runtime.h>
#include <cuda_bf16.h>
#include <math.h>

// ---------------- problem constants ----------------
#define BB    8
#define FREQ  257
#define TT    1345
#define NF    128
#define NS    64
#define NW    20          // (1345-128-1)/64 + 1
#define WIN   (BB*NW)     // 160
#define C1    8
#define P1H   84
#define P1W   41
#define C2    16
#define P2H   28
#define P2W   14
#define HID   6272        // 16*28*14
#define G3    (3*HID)     // 18816

#define GRU_BLOCKS 148
#define GRU_WARPS  16
#define GRU_SLOTS  (GRU_BLOCKS*GRU_WARPS)        // 2368 warp slots
#define GRU_SMEM   (4*HID*(int)sizeof(float2))   // 200704 B
#define PASS1_UNITS (2*GRU_SLOTS)                // 4736
#define PASS2_UNITS (HID - PASS1_UNITS)          // 1536

// packed fp32x2 FMA: acc = a*b + acc (two full-precision fp32 FMAs, 1 instr)
#define FFMA2ACC(acc, a, b) asm("fma.rn.f32x2 %0, %1, %2, %0;" \
    : "+l"(*(unsigned long long*)&(acc)) \
    : "l"(*(const unsigned long long*)&(a)), "l"(*(const unsigned long long*)&(b)))

// ---------------- device scratch (no allocation allowed) ----------------
__device__ float g_P1[WIN * C1 * P1H * P1W];   // 160*8*84*41
__device__ float g_FEATS[WIN * HID];           // 160*6272
__device__ float g_GI[(size_t)WIN * G3];       // 160*18816
__device__ float g_H[2][BB * HID];             // ping-pong hidden state

// =====================================================================
// K1: conv1 (1->8ch, 9x9, pad2) + maxpool3 + leaky_relu, fused.
// =====================================================================
__global__ void conv1_kernel(const float* __restrict__ x,
                             const float* __restrict__ w,
                             const float* __restrict__ bias)
{
    __shared__ float tile[11][132];
    __shared__ float Ws[C1][9][9];

    const int pr  = blockIdx.x;        // pooled row 0..83
    const int win = blockIdx.y;        // 0..159
    const int b   = win / NW;
    const int wdx = win % NW;
    const int tid = threadIdx.y * 41 + threadIdx.x;   // 0..327

    for (int i = tid; i < C1 * 81; i += 328)
        ((float*)Ws)[i] = w[i];

    const float* xb = x + (size_t)b * FREQ * TT + TT + wdx * NS;
    const int r0 = 3 * pr - 2;
    for (int i = tid; i < 11 * 132; i += 328) {
        int r = i / 132, c = i % 132;
        int gr = r0 + r, gc = c - 2;
        float v = 0.f;
        if (gr >= 0 && gr < 256 && gc >= 0 && gc < NF)
            v = xb[(size_t)gr * TT + gc];
        tile[r][c] = v;
    }
    __syncthreads();

    const int ch = threadIdx.y;
    const int tc = threadIdx.x;
    const float bv = bias[ch];
    float acc[3][3];
#pragma unroll
    for (int i = 0; i < 3; i++)
#pragma unroll
        for (int j = 0; j < 3; j++) acc[i][j] = bv;

#pragma unroll
    for (int r = 0; r < 11; r++) {
        float v[11];
#pragma unroll
        for (int m = 0; m < 11; m++) v[m] = tile[r][3 * tc + m];
#pragma unroll
        for (int i = 0; i < 3; i++) {
            const int kr = r - i;
            if (kr >= 0 && kr <= 8) {
#pragma unroll
                for (int kc = 0; kc < 9; kc++) {
                    float wv = Ws[ch][kr][kc];
                    acc[i][0] = fmaf(wv, v[kc],     acc[i][0]);
                    acc[i][1] = fmaf(wv, v[kc + 1], acc[i][1]);
                    acc[i][2] = fmaf(wv, v[kc + 2], acc[i][2]);
                }
            }
        }
    }
    float m = acc[0][0];
#pragma unroll
    for (int i = 0; i < 3; i++)
#pragma unroll
        for (int j = 0; j < 3; j++) m = fmaxf(m, acc[i][j]);
    float o = (m > 0.f) ? m : 0.01f * m;
    g_P1[(((size_t)win * C1 + ch) * P1H + pr) * P1W + tc] = o;
}

// =====================================================================
// K2: conv2 (8->16ch, 4x4, pad2) + maxpool3 + leaky_relu, fused.
// =====================================================================
__global__ void conv2_kernel(const float* __restrict__ w,
                             const float* __restrict__ bias)
{
    __shared__ float tile[C1][6][46];
    __shared__ float Ws[C2][C1][4][4];

    const int pr  = blockIdx.x;
    const int win = blockIdx.y;
    const int tid = threadIdx.y * 14 + threadIdx.x;   // 0..223

    for (int i = tid; i < C2 * C1 * 16; i += 224)
        ((float*)Ws)[i] = w[i];

    const float* src = g_P1 + (size_t)win * C1 * P1H * P1W;
    const int r0 = 3 * pr - 2;
    for (int i = tid; i < C1 * 6 * 46; i += 224) {
        int ich = i / (6 * 46);
        int rem = i % (6 * 46);
        int r = rem / 46, c = rem % 46;
        int gr = r0 + r, gc = c - 2;
        float v = 0.f;
        if (gr >= 0 && gr < P1H && gc >= 0 && gc < P1W)
            v = src[((size_t)ich * P1H + gr) * P1W + gc];
        tile[ich][r][c] = v;
    }
    __syncthreads();

    const int pc = threadIdx.x;
    const int oc = threadIdx.y;
    const float bv = bias[oc];
    float acc[3][3];
#pragma unroll
    for (int i = 0; i < 3; i++)
#pragma unroll
        for (int j = 0; j < 3; j++) acc[i][j] = bv;

#pragma unroll
    for (int ich = 0; ich < C1; ich++) {
#pragma unroll
        for (int r = 0; r < 6; r++) {
            float v[6];
#pragma unroll
            for (int m = 0; m < 6; m++) v[m] = tile[ich][r][3 * pc + m];
#pragma unroll
            for (int i = 0; i < 3; i++) {
                const int kr = r - i;
                if (kr >= 0 && kr <= 3) {
#pragma unroll
                    for (int kc = 0; kc < 4; kc++) {
                        float wv = Ws[oc][ich][kr][kc];
                        acc[i][0] = fmaf(wv, v[kc],     acc[i][0]);
                        acc[i][1] = fmaf(wv, v[kc + 1], acc[i][1]);
                        acc[i][2] = fmaf(wv, v[kc + 2], acc[i][2]);
                    }
                }
            }
        }
    }
    float m = acc[0][0];
#pragma unroll
    for (int i = 0; i < 3; i++)
#pragma unroll
        for (int j = 0; j < 3; j++) m = fmaxf(m, acc[i][j]);
    float o = (m > 0.f) ? m : 0.01f * m;
    g_FEATS[(size_t)win * HID + oc * (P2H * P2W) + pr * P2W + pc] = o;
}

// =====================================================================
// K3: GI = FEATS(160x6272) @ w_ih^T(6272x18816) + b_ih   (R4 version)
// BM=160, BN=128, BK=16; 256 threads, 10x8 per thread, plain FFMA.
// =====================================================================
__global__ __launch_bounds__(256, 2)
void gi_gemm_kernel(const float* __restrict__ Wih,
                    const float* __restrict__ bih)
{
    __shared__ float As[16][160];
    __shared__ float Bs[16][128];

    const int n0 = blockIdx.x * 128;
    const int tid = threadIdx.x;
    const int ty = tid >> 4;      // 0..15 -> M group (10 rows)
    const int tx = tid & 15;      // 0..15 -> N group (8 cols)

    float acc[10][8];
#pragma unroll
    for (int i = 0; i < 10; i++)
#pragma unroll
        for (int u = 0; u < 8; u++) acc[i][u] = 0.f;

    for (int k0 = 0; k0 < HID; k0 += 16) {
#pragma unroll
        for (int l = 0; l < 10; l++) {
            int idx = tid + l * 256;          // 0..2559
            int m = idx >> 4, kk = idx & 15;
            As[kk][m] = g_FEATS[(size_t)m * HID + k0 + kk];
        }
#pragma unroll
        for (int l = 0; l < 8; l++) {
            int idx = tid + l * 256;          // 0..2047
            int n = idx >> 4, kk = idx & 15;
            Bs[kk][n] = Wih[(size_t)(n0 + n) * HID + k0 + kk];
        }
        __syncthreads();

#pragma unroll
        for (int kk = 0; kk < 16; kk++) {
            float4 b0 = *(const float4*)&Bs[kk][tx * 8];
            float4 b1 = *(const float4*)&Bs[kk][tx * 8 + 4];
            float bb[8] = {b0.x, b0.y, b0.z, b0.w, b1.x, b1.y, b1.z, b1.w};
            float a[10];
#pragma unroll
            for (int i = 0; i < 10; i++) a[i] = As[kk][ty * 10 + i];
#pragma unroll
            for (int i = 0; i < 10; i++)
#pragma unroll
                for (int u = 0; u < 8; u++)
                    acc[i][u] = fmaf(a[i], bb[u], acc[i][u]);
        }
        __syncthreads();
    }

#pragma unroll
    for (int i = 0; i < 10; i++) {
        int m = ty * 10 + i;
#pragma unroll
        for (int u = 0; u < 8; u++) {
            int n = n0 + tx * 8 + u;
            g_GI[(size_t)m * G3 + n] = acc[i][u] + bih[n];
        }
    }
}

// =====================================================================
// K4: one GRU step. grid 148, block 512 (16 warps), h resident in 200KB
// dynamic smem as batch-paired float2. w_hh streamed as LDG.128 float4,
// each warp computes 2 hidden units per pass (JU=2) to amortize LDS.
// =====================================================================
struct GateAcc { float2 a[4]; };

__device__ __forceinline__ void gru_epilogue(
    int j, int lane, const float2* hp,
    const GateAcc& R, const GateAcc& Z, const GateAcc& N,
    const float* __restrict__ bhh, int t, float* __restrict__ hout)
{
    // butterfly reduce 24 components
    float rx[4], ry[4], zx[4], zy[4], nx[4], ny[4];
#pragma unroll
    for (int p = 0; p < 4; p++) {
        rx[p] = R.a[p].x; ry[p] = R.a[p].y;
        zx[p] = Z.a[p].x; zy[p] = Z.a[p].y;
        nx[p] = N.a[p].x; ny[p] = N.a[p].y;
#pragma unroll
        for (int off = 16; off > 0; off >>= 1) {
            rx[p] += __shfl_xor_sync(0xffffffffu, rx[p], off);
            ry[p] += __shfl_xor_sync(0xffffffffu, ry[p], off);
            zx[p] += __shfl_xor_sync(0xffffffffu, zx[p], off);
            zy[p] += __shfl_xor_sync(0xffffffffu, zy[p], off);
            nx[p] += __shfl_xor_sync(0xffffffffu, nx[p], off);
            ny[p] += __shfl_xor_sync(0xffffffffu, ny[p], off);
        }
    }
    if (lane < BB) {
        const int b = lane, p = b >> 1;
        const bool hi = b & 1;
        float hr = (hi ? ry[p] : rx[p]) + bhh[j];
        float hz = (hi ? zy[p] : zx[p]) + bhh[j + HID];
        float hn = (hi ? ny[p] : nx[p]) + bhh[j + 2 * HID];
        const float* gib = g_GI + (size_t)(b * NW + t) * G3;
        float r = 1.f / (1.f + expf(-(gib[j] + hr)));
        float z = 1.f / (1.f + expf(-(gib[j + HID] + hz)));
        float n = tanhf(gib[j + 2 * HID] + r * hn);
        float2 hj = hp[p * HID + j];
        float ho = hi ? hj.y : hj.x;
        hout[(size_t)b * HID + j] = (1.f - z) * n + z * ho;
    }
}

__global__ __launch_bounds__(512, 1)
void gru_step_kernel(const float* __restrict__ Whh,
                     const float* __restrict__ bhh,
                     const float* __restrict__ h0,
                     int t)
{
    extern __shared__ float2 hp[];   // [4][HID]: hp[p][k] = {h[2p][k], h[2p+1][k]}

    const float* hin  = (t == 0) ? h0 : g_H[(t + 1) & 1];
    float*       hout = g_H[t & 1];
    const int tid = threadIdx.x;

    // fill paired h (200KB), coalesced float4 reads
#pragma unroll
    for (int p = 0; p < 4; p++) {
        const float4* r0 = (const float4*)(hin + (size_t)(2 * p) * HID);
        const float4* r1 = (const float4*)(hin + (size_t)(2 * p + 1) * HID);
        for (int q = tid; q < HID / 4; q += 512) {
            float4 a = r0[q], b = r1[q];
            float2* dst = &hp[p * HID + q * 4];
            dst[0] = make_float2(a.x, b.x);
            dst[1] = make_float2(a.y, b.y);
            dst[2] = make_float2(a.z, b.z);
            dst[3] = make_float2(a.w, b.w);
        }
    }
    __syncthreads();

    const int warpId = tid >> 5;
    const int lane   = tid & 31;
    const int slot   = blockIdx.x * GRU_WARPS + warpId;   // 0..2367

    // ---------------- pass 1: JU=2, units jA=2*slot, jB=2*slot+1 ----------------
    {
        const int jA = 2 * slot, jB = 2 * slot + 1;
        const float4* wrA = (const float4*)(Whh + (size_t)jA * HID);
        const float4* wzA = (const float4*)(Whh + (size_t)(jA + HID) * HID);
        const float4* wnA = (const float4*)(Whh + (size_t)(jA + 2 * HID) * HID);
        const float4* wrB = (const float4*)(Whh + (size_t)jB * HID);
        const float4* wzB = (const float4*)(Whh + (size_t)(jB + HID) * HID);
        const float4* wnB = (const float4*)(Whh + (size_t)(jB + 2 * HID) * HID);

        GateAcc RA, ZA, NA, RB, ZB, NB;
#pragma unroll
        for (int p = 0; p < 4; p++) {
            RA.a[p] = make_float2(0.f, 0.f); ZA.a[p] = make_float2(0.f, 0.f);
            NA.a[p] = make_float2(0.f, 0.f); RB.a[p] = make_float2(0.f, 0.f);
            ZB.a[p] = make_float2(0.f, 0.f); NB.a[p] = make_float2(0.f, 0.f);
        }

#pragma unroll 2
        for (int it = 0; it < HID / 128; it++) {       // 49 iters
            const int q = it * 32 + lane;              // float4 index
            float4 ra = __ldcs(wrA + q), za = __ldcs(wzA + q), na = __ldcs(wnA + q);
            float4 rb = __ldcs(wrB + q), zb = __ldcs(wzB + q), nb = __ldcs(wnB + q);
            const int k = q * 4;
#pragma unroll
            for (int p = 0; p < 4; p++) {
                const float2* hpp = &hp[p * HID + k];
                float2 h0v = hpp[0], h1v = hpp[1], h2v = hpp[2], h3v = hpp[3];
                float2 w2;
                w2 = make_float2(ra.x, ra.x); FFMA2ACC(RA.a[p], w2, h0v);
                w2 = make_float2(ra.y, ra.y); FFMA2ACC(RA.a[p], w2, h1v);
                w2 = make_float2(ra.z, ra.z); FFMA2ACC(RA.a[p], w2, h2v);
                w2 = make_float2(ra.w, ra.w); FFMA2ACC(RA.a[p], w2, h3v);
                w2 = make_float2(za.x, za.x); FFMA2ACC(ZA.a[p], w2, h0v);
                w2 = make_float2(za.y, za.y); FFMA2ACC(ZA.a[p], w2, h1v);
                w2 = make_float2(za.z, za.z); FFMA2ACC(ZA.a[p], w2, h2v);
                w2 = make_float2(za.w, za.w); FFMA2ACC(ZA.a[p], w2, h3v);
                w2 = make_float2(na.x, na.x); FFMA2ACC(NA.a[p], w2, h0v);
                w2 = make_float2(na.y, na.y); FFMA2ACC(NA.a[p], w2, h1v);
                w2 = make_float2(na.z, na.z); FFMA2ACC(NA.a[p], w2, h2v);
                w2 = make_float2(na.w, na.w); FFMA2ACC(NA.a[p], w2, h3v);
                w2 = make_float2(rb.x, rb.x); FFMA2ACC(RB.a[p], w2, h0v);
                w2 = make_float2(rb.y, rb.y); FFMA2ACC(RB.a[p], w2, h1v);
                w2 = make_float2(rb.z, rb.z); FFMA2ACC(RB.a[p], w2, h2v);
                w2 = make_float2(rb.w, rb.w); FFMA2ACC(RB.a[p], w2, h3v);
                w2 = make_float2(zb.x, zb.x); FFMA2ACC(ZB.a[p], w2, h0v);
                w2 = make_float2(zb.y, zb.y); FFMA2ACC(ZB.a[p], w2, h1v);
                w2 = make_float2(zb.z, zb.z); FFMA2ACC(ZB.a[p], w2, h2v);
                w2 = make_float2(zb.w, zb.w); FFMA2ACC(ZB.a[p], w2, h3v);
                w2 = make_float2(nb.x, nb.x); FFMA2ACC(NB.a[p], w2, h0v);
                w2 = make_float2(nb.y, nb.y); FFMA2ACC(NB.a[p], w2, h1v);
                w2 = make_float2(nb.z, nb.z); FFMA2ACC(NB.a[p], w2, h2v);
                w2 = make_float2(nb.w, nb.w); FFMA2ACC(NB.a[p], w2, h3v);
            }
        }
        gru_epilogue(jA, lane, hp, RA, ZA, NA, bhh, t, hout);
        gru_epilogue(jB, lane, hp, RB, ZB, NB, bhh, t, hout);
    }

    // ---------------- pass 2: JU=1, unit j = 4736 + slot (slot < 1536) ----------------
    if (slot < PASS2_UNITS) {
        const int j = PASS1_UNITS + slot;
        const float4* wr = (const float4*)(Whh + (size_t)j * HID);
        const float4* wz = (const float4*)(Whh + (size_t)(j + HID) * HID);
        const float4* wn = (const float4*)(Whh + (size_t)(j + 2 * HID) * HID);

        GateAcc R, Z, N;
#pragma unroll
        for (int p = 0; p < 4; p++) {
            R.a[p] = make_float2(0.f, 0.f);
            Z.a[p] = make_float2(0.f, 0.f);
            N.a[p] = make_float2(0.f, 0.f);
        }

#pragma unroll 2
        for (int it = 0; it < HID / 128; it++) {
            const int q = it * 32 + lane;
            float4 rw = __ldcs(wr + q), zw = __ldcs(wz + q), nw = __ldcs(wn + q);
            const int k = q * 4;
#pragma unroll
            for (int p = 0; p < 4; p++) {
                const float2* hpp = &hp[p * HID + k];
                float2 h0v = hpp[0], h1v = hpp[1], h2v = hpp[2], h3v = hpp[3];
                float2 w2;
                w2 = make_float2(rw.x, rw.x); FFMA2ACC(R.a[p], w2, h0v);
                w2 = make_float2(rw.y, rw.y); FFMA2ACC(R.a[p], w2, h1v);
                w2 = make_float2(rw.z, rw.z); FFMA2ACC(R.a[p], w2, h2v);
                w2 = make_float2(rw.w, rw.w); FFMA2ACC(R.a[p], w2, h3v);
                w2 = make_float2(zw.x, zw.x); FFMA2ACC(Z.a[p], w2, h0v);
                w2 = make_float2(zw.y, zw.y); FFMA2ACC(Z.a[p], w2, h1v);
                w2 = make_float2(zw.z, zw.z); FFMA2ACC(Z.a[p], w2, h2v);
                w2 = make_float2(zw.w, zw.w); FFMA2ACC(Z.a[p], w2, h3v);
                w2 = make_float2(nw.x, nw.x); FFMA2ACC(N.a[p], w2, h0v);
                w2 = make_float2(nw.y, nw.y); FFMA2ACC(N.a[p], w2, h1v);
                w2 = make_float2(nw.z, nw.z); FFMA2ACC(N.a[p], w2, h2v);
                w2 = make_float2(nw.w, nw.w); FFMA2ACC(N.a[p], w2, h3v);
            }
        }
        gru_epilogue(j, lane, hp, R, Z, N, bhh, t, hout);
    }
}

// =====================================================================
// K5: samples = h @ fc2_w^T + fc2_b ; labels (int32) appended as float32.
// =====================================================================
__global__ void final_fc_kernel(const float* __restrict__ fw,
                                const float* __restrict__ fb,
                                const int* __restrict__ labels,
                                float* __restrict__ out)
{
    const float* h = g_H[(NW - 1) & 1];   // g_H[1]
    const int warpId = threadIdx.x >> 5;
    const int lane   = threadIdx.x & 31;

    for (int p = warpId; p < BB * 10; p += 8) {
        int b = p / 10, c = p % 10;
        const float* hb = h + (size_t)b * HID;
        const float* wc = fw + (size_t)c * HID;
        float s = 0.f;
        for (int k = lane; k < HID; k += 32)
            s = fmaf(hb[k], wc[k], s);
#pragma unroll
        for (int off = 16; off > 0; off >>= 1)
            s += __shfl_xor_sync(0xffffffffu, s, off);
        if (lane == 0)
            out[b * 10 + c] = s + fb[c];
    }
    if (threadIdx.x < BB)
        out[BB * 10 + threadIdx.x] = (float)labels[threadIdx.x];
}

// =====================================================================
extern "C" void kernel_launch(void* const* d_in, const int* in_sizes, int n_in,
                              void* d_out, int out_size)
{
    const float* x       = (const float*)d_in[0];
    const int*   labels  = (const int*)d_in[1];
    const float* h0      = (const float*)d_in[2];
    const float* conv1_w = (const float*)d_in[3];
    const float* conv1_b = (const float*)d_in[4];
    const float* conv2_w = (const float*)d_in[5];
    const float* conv2_b = (const float*)d_in[6];
    const float* w_ih    = (const float*)d_in[7];
    const float* w_hh    = (const float*)d_in[8];
    const float* b_ih    = (const float*)d_in[9];
    const float* b_hh    = (const float*)d_in[10];
    const float* fc2_w   = (const float*)d_in[11];
    const float* fc2_b   = (const float*)d_in[12];
    float*       out     = (float*)d_out;

    cudaFuncSetAttribute(gru_step_kernel,
                         cudaFuncAttributeMaxDynamicSharedMemorySize, GRU_SMEM);

    conv1_kernel<<<dim3(P1H, WIN), dim3(41, 8)>>>(x, conv1_w, conv1_b);
    conv2_kernel<<<dim3(P2H, WIN), dim3(14, 16)>>>(conv2_w, conv2_b);
    gi_gemm_kernel<<<G3 / 128, 256>>>(w_ih, b_ih);
    for (int t = 0; t < NW; t++)
        gru_step_kernel<<<GRU_BLOCKS, 512, GRU_SMEM>>>(w_hh, b_hh, h0, t);
    final_fc_kernel<<<1, 256>>>(fc2_w, fc2_b, labels, out);
}